// round 6
// baseline (speedup 1.0000x reference)
#include <cuda_runtime.h>
#include <math.h>

// Problem geometry (static: x shape (1, 3, 32, 512, 512), patch 32x32)
#define C       3
#define T       32
#define H       512
#define W       512
#define PS      32              // hc = wc = 32
#define NH      (H / PS)        // 16
#define NW      (W / PS)        // 16
#define NPATCH  (T * NH * NW)   // 8192
#define PATCH_ELEMS (C * PS * PS) // 3072

// Per-frame running max of patch sums (float bits; all sums >= 0, so
// int-punned atomicMax preserves float ordering and zero-init is correct).
// Reset by the finalize kernel each iteration -> graph-replay safe.
__device__ int g_frame_max[T];   // zero-initialized at module load

// ---------------------------------------------------------------------------
// K1: one CTA per patch. 256 threads, each loads 3 float4 pairs (one per
// channel), block-reduce, then ONE fire-and-forget RED.MAX per CTA.
// No fence, no counter, no return value -> no L2 round-trip wait.
// ---------------------------------------------------------------------------
__global__ __launch_bounds__(256, 8)
void patch_sum_kernel(const float* __restrict__ x,
                      const float* __restrict__ xr) {
    const int patch = blockIdx.x;          // [0, 8192)
    const int t   = patch >> 8;            // frame
    const int rem = patch & 255;
    const int ih  = rem >> 4;
    const int iw  = rem & 15;

    const int tid = threadIdx.x;           // [0, 256)
    const int r = tid >> 3;                // row within patch [0,32)
    const int q = tid & 7;                 // float4 index within row [0,8)

    const int hrow = ih * PS + r;
    const int wcol = iw * PS + q * 4;
    const int base0 = (t * H + hrow) * W + wcol;        // channel 0
    const int cstride = T * H * W;

    float s = 0.0f;
#pragma unroll
    for (int c = 0; c < C; ++c) {
        const int idx = base0 + c * cstride;
        const float4 a = __ldg(reinterpret_cast<const float4*>(x  + idx));
        const float4 b = __ldg(reinterpret_cast<const float4*>(xr + idx));
        s += fabsf(a.x - b.x) + fabsf(a.y - b.y)
           + fabsf(a.z - b.z) + fabsf(a.w - b.w);
    }

    // Block reduction: warp shfl then smem across 8 warps.
#pragma unroll
    for (int off = 16; off > 0; off >>= 1)
        s += __shfl_down_sync(0xFFFFFFFFu, s, off);

    __shared__ float warp_sums[8];
    const int lane = tid & 31;
    const int wid  = tid >> 5;
    if (lane == 0) warp_sums[wid] = s;
    __syncthreads();

    if (wid == 0) {
        float v = (lane < 8) ? warp_sums[lane] : 0.0f;
#pragma unroll
        for (int off = 4; off > 0; off >>= 1)
            v += __shfl_down_sync(0xFFFFFFFFu, v, off);
        if (lane == 0) {
            // v >= 0 -> int compare == float compare. Unused return -> RED.MAX.
            atomicMax(&g_frame_max[t], __float_as_int(v));
        }
    }

#if __CUDA_ARCH__ >= 900
    // Let the PDL-dependent finalize kernel begin its launch/prologue early.
    cudaTriggerProgrammaticLaunchCompletion();
#endif
}

// ---------------------------------------------------------------------------
// K2 (PDL secondary): 1 warp. Wait for K1's memory, reduce 32 frame maxima,
// log, store scalar, and reset g_frame_max for the next graph replay.
// ---------------------------------------------------------------------------
__global__ __launch_bounds__(32, 1)
void patch_final_kernel(float* __restrict__ out) {
#if __CUDA_ARCH__ >= 900
    cudaGridDependencySynchronize();   // all K1 atomics visible after this
#endif
    const int lane = threadIdx.x;      // [0, 32)

    float v = fmaxf(__int_as_float(__ldcg(&g_frame_max[lane])), 0.0f);
#pragma unroll
    for (int off = 16; off > 0; off >>= 1)
        v += __shfl_down_sync(0xFFFFFFFFu, v, off);

    // Reset state (each thread already consumed its slot).
    g_frame_max[lane] = 0;

    if (lane == 0) {
        const float scale = 0.5f / ((float)PATCH_ELEMS * (float)T);
        out[0] = logf(v * scale);
    }
}

extern "C" void kernel_launch(void* const* d_in, const int* in_sizes, int n_in,
                              void* d_out, int out_size) {
    const float* x  = (const float*)d_in[0];
    const float* xr = (const float*)d_in[1];
    float* out = (float*)d_out;

    patch_sum_kernel<<<NPATCH, 256>>>(x, xr);

    // Finalize with Programmatic Dependent Launch so its launch latency
    // overlaps K1's execution; cudaGridDependencySynchronize() inside K2
    // provides the data dependency.
    cudaLaunchConfig_t cfg = {};
    cfg.gridDim  = dim3(1, 1, 1);
    cfg.blockDim = dim3(32, 1, 1);
    cfg.dynamicSmemBytes = 0;
    cfg.stream = 0;
    cudaLaunchAttribute attr[1];
    attr[0].id = cudaLaunchAttributeProgrammaticStreamSerialization;
    attr[0].val.programmaticStreamSerializationAllowed = 1;
    cfg.attrs = attr;
    cfg.numAttrs = 1;
    cudaError_t e = cudaLaunchKernelEx(&cfg, patch_final_kernel, out);
    if (e != cudaSuccess) {
        // Fallback: plain serialized launch (still correct).
        patch_final_kernel<<<1, 32>>>(out);
    }
}